// round 14
// baseline (speedup 1.0000x reference)
#include <cuda_runtime.h>
#include <cuda_bf16.h>

// MaskFiller: out[b, keep_ids[b,k], :] = inputs[b,k,:]
//             out[b, mask_ids[b,m], :] = mask_embedding[:]
// B=8, K=4096, M=4096, L=8192, D=512 (f32). Pure data movement; HBM bound.
//
// R10: scatter -> gather inversion. R4/R9 both plateaued at DRAM 64%,
// kernel ~28us, regardless of unroll depth -> latency fully hidden, limit
// is HBM efficiency under mixed scattered-write traffic. This version
// builds the inverse permutation (tiny L2-resident scatter), then gathers:
// output writes become perfectly sequential streaming; the scatter moves
// to the read side, which tolerates it (MLP-deep reads, 2KB granularity).
//
// Inputs (metadata order):
//   d_in[0] inputs            float32 [B, K, D]
//   d_in[1] mask_position_ids int32   [B, M]
//   d_in[2] keep_position_ids int32   [B, K]
//   d_in[3] mask_embedding    float32 [D]
//   d_in[4] axis              (unused; always -2)

#define B_ 8
#define K_ 4096
#define M_ 4096
#define L_ (K_ + M_)
#define D_ 512
#define VPR 128          // float4 per row (D/4)
#define U_  8            // output rows per CTA in the gather kernel

// Inverse map: g_inv[b*L + l] = input row j (if keep slot) or -1 (mask slot).
// 256 KB static scratch; fully rewritten every launch -> deterministic.
__device__ int g_inv[B_ * L_];

__global__ __launch_bounds__(256)
void build_inv_kernel(const int* __restrict__ mask_ids,
                      const int* __restrict__ keep_ids)
{
    const int t = blockIdx.x * 256 + threadIdx.x;   // 0 .. B*L-1
    const int b = t >> 13;                          // t / L_
    const int j = t & (L_ - 1);                     // t % L_
    if (j < K_) {
        const int pos = __ldg(&keep_ids[b * K_ + j]);
        g_inv[b * L_ + pos] = j;
    } else {
        const int pos = __ldg(&mask_ids[b * M_ + (j - K_)]);
        g_inv[b * L_ + pos] = -1;
    }
}

__global__ __launch_bounds__(128, 8)
void gather_kernel(const float4* __restrict__ inputs,
                   const float4* __restrict__ mask_emb,
                   float4*       __restrict__ out)
{
    // CTA writes U_ consecutive output rows l0..l0+7 of batch b.
    const int t0  = blockIdx.x * U_;
    const int b   = t0 >> 13;            // t0 / L_
    const int l0  = t0 & (L_ - 1);       // t0 % L_
    const int tid = threadIdx.x;         // 0..127, one float4 column

    // Source rows: sequential read of the L2-resident inverse map.
    int src[U_];
    #pragma unroll
    for (int u = 0; u < U_; ++u)
        src[u] = __ldg(&g_inv[b * L_ + l0 + u]);

    const float4 emb = __ldg(&mask_emb[tid]);      // L2/L1 resident
    const float4* __restrict__ in_b = inputs + (size_t)b * K_ * VPR;

    // Gather: scattered reads, U_-deep MLP. Mask rows take the register
    // broadcast instead (per-row uniform across the CTA).
    float4 v[U_];
    #pragma unroll
    for (int u = 0; u < U_; ++u)
        v[u] = (src[u] >= 0) ? __ldcs(&in_b[(size_t)src[u] * VPR + tid]) : emb;

    // Perfectly sequential streaming writes.
    float4* __restrict__ dst = out + ((size_t)b * L_ + l0) * VPR + tid;
    #pragma unroll
    for (int u = 0; u < U_; ++u)
        __stcs(dst + u * VPR, v[u]);
}

extern "C" void kernel_launch(void* const* d_in, const int* in_sizes, int n_in,
                              void* d_out, int out_size)
{
    const float4* inputs   = (const float4*)d_in[0];
    const int*    mask_ids = (const int*)   d_in[1];
    const int*    keep_ids = (const int*)   d_in[2];
    const float4* mask_emb = (const float4*)d_in[3];
    float4*       out      = (float4*)      d_out;

    (void)in_sizes; (void)n_in; (void)out_size;

    // Phase 1: build inverse permutation (0.5 MB scatter into 256 KB scratch).
    build_inv_kernel<<<(B_ * L_) / 256, 256>>>(mask_ids, keep_ids);

    // Phase 2: gather with linear output writes. 8192 CTAs x 128 threads.
    gather_kernel<<<(B_ * L_) / U_, 128>>>(inputs, mask_emb, out);
}

// round 15
// speedup vs baseline: 1.1089x; 1.1089x over previous
#include <cuda_runtime.h>
#include <cuda_bf16.h>

// MaskFiller: out[b, keep_ids[b,k], :] = inputs[b,k,:]
//             out[b, mask_ids[b,m], :] = mask_embedding[:]
// B=8, K=4096, M=4096, L=8192, D=512 (f32). Pure scatter-copy; HBM bound.
//
// R14: revert to R4 scatter geometry (U=4, best occupancy; gather in R10
// regressed -- scattered reads are latency-exposed, scattered writes are
// not). Single change vs R4: input loads use __ldg (evict-normal) instead
// of __ldcs. The 64MB input fits in the 126MB L2 and is re-read every
// graph replay; marking it evict-first was discarding that reuse while the
// 128MB evict-first (__stcs) write stream churned through. ncu already
// showed ~50MB/replay of reads L2-hitting; this should make it ~all of it,
// leaving DRAM with (mostly) the write stream only.
//
// Inputs (metadata order):
//   d_in[0] inputs            float32 [B, K, D]
//   d_in[1] mask_position_ids int32   [B, M]
//   d_in[2] keep_position_ids int32   [B, K]
//   d_in[3] mask_embedding    float32 [D]
//   d_in[4] axis              (unused; always -2)

#define B_ 8
#define K_ 4096
#define M_ 4096
#define L_ (K_ + M_)
#define D_ 512
#define VPR 128          // float4 per row (D/4)
#define U_  4            // rows per CTA

__global__ __launch_bounds__(128, 16)
void maskfiller_kernel(const float4* __restrict__ inputs,
                       const int*    __restrict__ mask_ids,
                       const int*    __restrict__ keep_ids,
                       const float4* __restrict__ mask_emb,
                       float4*       __restrict__ out)
{
    // CTA handles U_ consecutive tasks. K_ and L_ are divisible by U_, so
    // all tasks in a CTA share the same batch b and the same branch.
    const int t0  = blockIdx.x * U_;
    const int b   = t0 >> 13;            // t0 / L_
    const int j0  = t0 & (L_ - 1);       // t0 % L_
    const int tid = threadIdx.x;         // 0..127, one float4 column

    float4* __restrict__ out_b = out + (size_t)b * L_ * VPR;

    if (j0 < K_) {
        // keep path: copy 4 input rows to scattered output rows.
        int rows[U_];
        #pragma unroll
        for (int u = 0; u < U_; ++u)
            rows[u] = __ldg(&keep_ids[b * K_ + j0 + u]);

        const float4* __restrict__ src =
            inputs + ((size_t)b * K_ + j0) * VPR + tid;
        float4 v[U_];
        #pragma unroll
        for (int u = 0; u < U_; ++u)
            v[u] = __ldg(src + u * VPR);   // evict-NORMAL: keep input in L2
                                           // across graph replays (64MB fits)

        #pragma unroll
        for (int u = 0; u < U_; ++u)
            __stcs(&out_b[(size_t)rows[u] * VPR + tid], v[u]);
    } else {
        // mask path: broadcast embedding into 4 scattered output rows.
        const float4 v = __ldg(&mask_emb[tid]);    // L2/L1 resident
        int rows[U_];
        #pragma unroll
        for (int u = 0; u < U_; ++u)
            rows[u] = __ldg(&mask_ids[b * M_ + (j0 - K_) + u]);

        #pragma unroll
        for (int u = 0; u < U_; ++u)
            __stcs(&out_b[(size_t)rows[u] * VPR + tid], v);
    }
}

extern "C" void kernel_launch(void* const* d_in, const int* in_sizes, int n_in,
                              void* d_out, int out_size)
{
    const float4* inputs   = (const float4*)d_in[0];
    const int*    mask_ids = (const int*)   d_in[1];
    const int*    keep_ids = (const int*)   d_in[2];
    const float4* mask_emb = (const float4*)d_in[3];
    float4*       out      = (float4*)      d_out;

    (void)in_sizes; (void)n_in; (void)out_size;

    // B*L / U_ = 16384 CTAs, 128 threads each, 4 rows per CTA.
    maskfiller_kernel<<<(B_ * L_) / U_, 128>>>(inputs, mask_ids, keep_ids,
                                               mask_emb, out);
}